// round 16
// baseline (speedup 1.0000x reference)
#include <cuda_runtime.h>
#include <math.h>

#define BB   4096
#define NN   64
#define DD   256
#define OUTD 512
#define NIT  3

// Transposed weight scratch
__device__ float g_w1t[DD * OUTD];    // [256][512]
__device__ float g_w2t[OUTD * OUTD];  // [512][512]

// ---- packed f32x2 helpers (sm_100+) ----
#define FMA2(d, a, b) asm("fma.rn.f32x2 %0, %1, %2, %0;" : "+l"(d) : "l"(a), "l"(b))
#define DUP2(d, s)    asm("mov.b64 %0, {%1, %1};" : "=l"(d) : "r"(s))
#define UNPK2(lo, hi, d) asm("mov.b64 {%0, %1}, %2;" : "=r"(lo), "=r"(hi) : "l"(d))

__device__ __forceinline__ float wsum(float v) {
    #pragma unroll
    for (int o = 16; o > 0; o >>= 1) v += __shfl_xor_sync(0xFFFFFFFFu, v, o);
    return v;
}

// ---------------------------------------------------------------------------
// Combined transpose for w1 (512x256) and w2 (512x512) in ONE launch.
// ---------------------------------------------------------------------------
__global__ void transpose2_kernel(const float* __restrict__ w1,
                                  const float* __restrict__ w2,
                                  float* __restrict__ w1t,
                                  float* __restrict__ w2t)
{
    __shared__ float tile[32][33];
    const float* in;
    float* out;
    int R, C, bid;
    if (blockIdx.x < 128) {
        in = w1; out = w1t; R = OUTD; C = DD; bid = blockIdx.x;
    } else {
        in = w2; out = w2t; R = OUTD; C = OUTD; bid = blockIdx.x - 128;
    }
    const int tilesX = C / 32;
    const int c0 = (bid % tilesX) * 32;
    const int r0 = (bid / tilesX) * 32;
    const int tx = threadIdx.x;
    const int ty = threadIdx.y;
    #pragma unroll
    for (int i = 0; i < 4; i++)
        tile[ty + 8 * i][tx] = in[(size_t)(r0 + ty + 8 * i) * C + c0 + tx];
    __syncthreads();
    #pragma unroll
    for (int i = 0; i < 4; i++)
        out[(size_t)(c0 + ty + 8 * i) * R + r0 + tx] = tile[tx][ty + 8 * i];
}

// ---------------------------------------------------------------------------
// Kernel 1: soft clustering. R15 structure; load phase interleaves each
// row's LDGs with its norm/mean partials to break the front-batched LDG
// burst (MLP_p1 8 -> ~2, per the L1tex-queue spread model).
// ---------------------------------------------------------------------------
__global__ void __launch_bounds__(512, 2)
cluster_kernel(const float* __restrict__ h,
               const float* __restrict__ log_tau,
               float* __restrict__ out_alpha,   // [B, 64]
               float* __restrict__ out_mu)      // [B, 256]
{
    __shared__ float pmu[16][DD];
    __shared__ float mu_s[DD];
    __shared__ float simv[NN];

    const int b = blockIdx.x;
    const int t = threadIdx.x;
    const int w = t >> 5;
    const int l = t & 31;

    const float* hb = h + (size_t)b * NN * DD;

    float tau = expf(log_tau[0]);
    tau = fminf(fmaxf(tau, 0.01f), 2.0f);
    const float inv_tau = 1.0f / tau;

    // --- interleaved load + per-row lanewise partials ---
    float4 hv[4][2];
    float nrm_p[4];           // lanewise square-sum partial per row
    float pm[8];
    #pragma unroll
    for (int i = 0; i < 8; i++) pm[i] = 0.0f;

    #pragma unroll
    for (int r = 0; r < 4; r++) {
        const float* p = hb + (size_t)(4 * w + r) * DD + 4 * l;
        hv[r][0] = *(const float4*)(p);
        hv[r][1] = *(const float4*)(p + 128);
        float4 a = hv[r][0], c = hv[r][1];
        nrm_p[r] = a.x*a.x + a.y*a.y + a.z*a.z + a.w*a.w
                 + c.x*c.x + c.y*c.y + c.z*c.z + c.w*c.w;
        pm[0] += a.x; pm[1] += a.y; pm[2] += a.z; pm[3] += a.w;
        pm[4] += c.x; pm[5] += c.y; pm[6] += c.z; pm[7] += c.w;
    }

    // --- per-row inverse norms via 4-way tree (9 shfl + 4 broadcasts) ---
    float rni[4];
    {
        float d[4];
        #pragma unroll
        for (int r = 0; r < 4; r++) d[r] = nrm_p[r];
        #pragma unroll
        for (int r = 0; r < 4; r++) d[r] += __shfl_xor_sync(0xFFFFFFFFu, d[r], 16);
        float p0 = (l & 16) ? d[1] : d[0];
        float p1 = (l & 16) ? d[3] : d[2];
        p0 += __shfl_xor_sync(0xFFFFFFFFu, p0, 8);
        p1 += __shfl_xor_sync(0xFFFFFFFFu, p1, 8);
        float q = (l & 8) ? p1 : p0;
        q += __shfl_xor_sync(0xFFFFFFFFu, q, 4);
        q += __shfl_xor_sync(0xFFFFFFFFu, q, 2);
        q += __shfl_xor_sync(0xFFFFFFFFu, q, 1);
        float s0 = __shfl_sync(0xFFFFFFFFu, q, 0);
        float s1 = __shfl_sync(0xFFFFFFFFu, q, 16);
        float s2 = __shfl_sync(0xFFFFFFFFu, q, 8);
        float s3 = __shfl_sync(0xFFFFFFFFu, q, 24);
        rni[0] = inv_tau / fmaxf(sqrtf(s0), 1e-12f);
        rni[1] = inv_tau / fmaxf(sqrtf(s1), 1e-12f);
        rni[2] = inv_tau / fmaxf(sqrtf(s2), 1e-12f);
        rni[3] = inv_tau / fmaxf(sqrtf(s3), 1e-12f);
    }

    // --- per-warp partial sums for initial mean ---
    *(float4*)&pmu[w][4 * l]       = make_float4(pm[0], pm[1], pm[2], pm[3]);
    *(float4*)&pmu[w][128 + 4 * l] = make_float4(pm[4], pm[5], pm[6], pm[7]);
    __syncthreads();

    if (t < DD) {
        float acc = 0.0f;
        #pragma unroll
        for (int ww = 0; ww < 16; ww++) acc += pmu[ww][t];
        mu_s[t] = acc * (1.0f / NN);
    }
    __syncthreads();

    for (int it = 0; it < NIT; it++) {
        float4 mn0 = *(const float4*)(mu_s + 4 * l);
        float4 mn1 = *(const float4*)(mu_s + 128 + 4 * l);
        float nq = mn0.x*mn0.x + mn0.y*mn0.y + mn0.z*mn0.z + mn0.w*mn0.w
                 + mn1.x*mn1.x + mn1.y*mn1.y + mn1.z*mn1.z + mn1.w*mn1.w;
        nq = wsum(nq);
        const float inv_nm = 1.0f / fmaxf(sqrtf(nq), 1e-12f);

        {
            float d[4];
            #pragma unroll
            for (int r = 0; r < 4; r++) {
                float4 a = hv[r][0], c = hv[r][1];
                d[r] = (a.x*mn0.x + a.y*mn0.y + a.z*mn0.z + a.w*mn0.w
                      + c.x*mn1.x + c.y*mn1.y + c.z*mn1.z + c.w*mn1.w) * rni[r];
            }
            #pragma unroll
            for (int r = 0; r < 4; r++) d[r] += __shfl_xor_sync(0xFFFFFFFFu, d[r], 16);
            float p0 = (l & 16) ? d[1] : d[0];
            float p1 = (l & 16) ? d[3] : d[2];
            p0 += __shfl_xor_sync(0xFFFFFFFFu, p0, 8);
            p1 += __shfl_xor_sync(0xFFFFFFFFu, p1, 8);
            float q = (l & 8) ? p1 : p0;
            q += __shfl_xor_sync(0xFFFFFFFFu, q, 4);
            q += __shfl_xor_sync(0xFFFFFFFFu, q, 2);
            q += __shfl_xor_sync(0xFFFFFFFFu, q, 1);
            const int rowmap = ((l >> 4) & 1) + (((l >> 3) & 1) << 1);
            if ((l & 7) == 0) simv[4 * w + rowmap] = q * inv_nm;
        }
        __syncthreads();

        // warp-redundant softmax over 64; shift by simv[0] (broadcast, exact)
        float s0 = simv[l];
        float s1 = simv[l + 32];
        const float shift = __shfl_sync(0xFFFFFFFFu, s0, 0);
        float e0 = expf(s0 - shift);
        float e1 = expf(s1 - shift);
        float inv = 1.0f / wsum(e0 + e1);
        float a_lo = e0 * inv;
        float a_hi = e1 * inv;

        if (it == NIT - 1 && w == 0) {
            out_alpha[(size_t)b * NN + l]      = a_lo;
            out_alpha[(size_t)b * NN + l + 32] = a_hi;
        }

        float al[4];
        if (w < 8) {
            #pragma unroll
            for (int r = 0; r < 4; r++)
                al[r] = __shfl_sync(0xFFFFFFFFu, a_lo, 4 * w + r);
        } else {
            #pragma unroll
            for (int r = 0; r < 4; r++)
                al[r] = __shfl_sync(0xFFFFFFFFu, a_hi, 4 * w + r - 32);
        }

        float pu[8];
        #pragma unroll
        for (int i = 0; i < 8; i++) pu[i] = 0.0f;
        #pragma unroll
        for (int r = 0; r < 4; r++) {
            const float a = al[r];
            pu[0] += a * hv[r][0].x; pu[1] += a * hv[r][0].y;
            pu[2] += a * hv[r][0].z; pu[3] += a * hv[r][0].w;
            pu[4] += a * hv[r][1].x; pu[5] += a * hv[r][1].y;
            pu[6] += a * hv[r][1].z; pu[7] += a * hv[r][1].w;
        }
        *(float4*)&pmu[w][4 * l]       = make_float4(pu[0], pu[1], pu[2], pu[3]);
        *(float4*)&pmu[w][128 + 4 * l] = make_float4(pu[4], pu[5], pu[6], pu[7]);
        __syncthreads();

        if (t < DD) {
            float acc = 0.0f;
            #pragma unroll
            for (int ww = 0; ww < 16; ww++) acc += pmu[ww][t];
            if (it == NIT - 1) out_mu[(size_t)b * DD + t] = acc;
            else               mu_s[t] = acc;
        }
        if (it < NIT - 1) __syncthreads();
    }
}

// ---------------------------------------------------------------------------
// Kernel 2: fused MLP (R11, unchanged). 256 thr, 8 rows, pipelined weights.
// ---------------------------------------------------------------------------
__global__ void __launch_bounds__(256, 3)
mlp_kernel(const float* __restrict__ mu_in,
           const float* __restrict__ b1,
           const float* __restrict__ g1,
           const float* __restrict__ be1,
           const float* __restrict__ b2,
           const float* __restrict__ g2,
           const float* __restrict__ be2,
           float* __restrict__ theta)
{
    __shared__ float xs[8 * OUTD];

    const int t = threadIdx.x;
    const int row0 = blockIdx.x * 8;
    const int ox4 = (t & 127) * 4;
    const int ry = (t >> 7) * 4;
    const int w = t >> 5;
    const int l = t & 31;

    {
        const float4* src = (const float4*)(mu_in + (size_t)row0 * DD);
        float4* dst = (float4*)xs;
        dst[t]       = src[t];
        dst[t + 256] = src[t + 256];
    }
    __syncthreads();

    unsigned long long a01[4], a23[4];
    #pragma unroll
    for (int r = 0; r < 4; r++) { a01[r] = 0ull; a23[r] = 0ull; }

    {
        const float* wb = g_w1t + ox4;
        ulonglong2 wA[4], wB[4];
        #pragma unroll
        for (int kk = 0; kk < 4; kk++)
            wA[kk] = *(const ulonglong2*)(wb + (size_t)kk * OUTD);

        for (int k = 0; k < DD; k += 8) {
            #pragma unroll
            for (int kk = 0; kk < 4; kk++)
                wB[kk] = *(const ulonglong2*)(wb + (size_t)(k + 4 + kk) * OUTD);
            {
                float4 m[4];
                #pragma unroll
                for (int r = 0; r < 4; r++)
                    m[r] = *(const float4*)(xs + (ry + r) * DD + k);
                #pragma unroll
                for (int kk = 0; kk < 4; kk++) {
                    #pragma unroll
                    for (int r = 0; r < 4; r++) {
                        float mv = (kk == 0) ? m[r].x : (kk == 1) ? m[r].y
                                 : (kk == 2) ? m[r].z : m[r].w;
                        unsigned long long d;
                        DUP2(d, __float_as_uint(mv));
                        FMA2(a01[r], wA[kk].x, d);
                        FMA2(a23[r], wA[kk].y, d);
                    }
                }
            }
            const int kn = (k + 8 < DD) ? k + 8 : k;
            #pragma unroll
            for (int kk = 0; kk < 4; kk++)
                wA[kk] = *(const ulonglong2*)(wb + (size_t)(kn + kk) * OUTD);
            {
                float4 m[4];
                #pragma unroll
                for (int r = 0; r < 4; r++)
                    m[r] = *(const float4*)(xs + (ry + r) * DD + k + 4);
                #pragma unroll
                for (int kk = 0; kk < 4; kk++) {
                    #pragma unroll
                    for (int r = 0; r < 4; r++) {
                        float mv = (kk == 0) ? m[r].x : (kk == 1) ? m[r].y
                                 : (kk == 2) ? m[r].z : m[r].w;
                        unsigned long long d;
                        DUP2(d, __float_as_uint(mv));
                        FMA2(a01[r], wB[kk].x, d);
                        FMA2(a23[r], wB[kk].y, d);
                    }
                }
            }
        }
    }
    __syncthreads();

    {
        const float4 bb = *(const float4*)(b1 + ox4);
        #pragma unroll
        for (int r = 0; r < 4; r++) {
            unsigned u0, u1, u2, u3;
            UNPK2(u0, u1, a01[r]);
            UNPK2(u2, u3, a23[r]);
            *(float4*)(xs + (ry + r) * OUTD + ox4) =
                make_float4(__uint_as_float(u0) + bb.x, __uint_as_float(u1) + bb.y,
                            __uint_as_float(u2) + bb.z, __uint_as_float(u3) + bb.w);
        }
    }
    __syncthreads();

    {
        const int row = w;
        float s = 0.0f, sq = 0.0f;
        #pragma unroll
        for (int j = 0; j < 16; j++) {
            float v = xs[row * OUTD + l + 32 * j];
            s += v; sq += v * v;
        }
        #pragma unroll
        for (int o = 16; o > 0; o >>= 1) {
            s  += __shfl_xor_sync(0xFFFFFFFFu, s, o);
            sq += __shfl_xor_sync(0xFFFFFFFFu, sq, o);
        }
        const float mean = s * (1.0f / OUTD);
        const float var  = sq * (1.0f / OUTD) - mean * mean;
        const float rstd = rsqrtf(var + 1e-5f);
        #pragma unroll
        for (int j = 0; j < 16; j++) {
            const int idx = l + 32 * j;
            float v = xs[row * OUTD + idx];
            v = (v - mean) * rstd * g1[idx] + be1[idx];
            v = 0.5f * v * (1.0f + erff(v * 0.70710678118654752f));
            xs[row * OUTD + idx] = v;
        }
    }
    __syncthreads();

    #pragma unroll
    for (int r = 0; r < 4; r++) { a01[r] = 0ull; a23[r] = 0ull; }

    {
        const float* wb = g_w2t + ox4;
        ulonglong2 wA[4], wB[4];
        #pragma unroll
        for (int kk = 0; kk < 4; kk++)
            wA[kk] = *(const ulonglong2*)(wb + (size_t)kk * OUTD);

        for (int k = 0; k < OUTD; k += 8) {
            #pragma unroll
            for (int kk = 0; kk < 4; kk++)
                wB[kk] = *(const ulonglong2*)(wb + (size_t)(k + 4 + kk) * OUTD);
            {
                float4 m[4];
                #pragma unroll
                for (int r = 0; r < 4; r++)
                    m[r] = *(const float4*)(xs + (ry + r) * OUTD + k);
                #pragma unroll
                for (int kk = 0; kk < 4; kk++) {
                    #pragma unroll
                    for (int r = 0; r < 4; r++) {
                        float mv = (kk == 0) ? m[r].x : (kk == 1) ? m[r].y
                                 : (kk == 2) ? m[r].z : m[r].w;
                        unsigned long long d;
                        DUP2(d, __float_as_uint(mv));
                        FMA2(a01[r], wA[kk].x, d);
                        FMA2(a23[r], wA[kk].y, d);
                    }
                }
            }
            const int kn = (k + 8 < OUTD) ? k + 8 : k;
            #pragma unroll
            for (int kk = 0; kk < 4; kk++)
                wA[kk] = *(const ulonglong2*)(wb + (size_t)(kn + kk) * OUTD);
            {
                float4 m[4];
                #pragma unroll
                for (int r = 0; r < 4; r++)
                    m[r] = *(const float4*)(xs + (ry + r) * OUTD + k + 4);
                #pragma unroll
                for (int kk = 0; kk < 4; kk++) {
                    #pragma unroll
                    for (int r = 0; r < 4; r++) {
                        float mv = (kk == 0) ? m[r].x : (kk == 1) ? m[r].y
                                 : (kk == 2) ? m[r].z : m[r].w;
                        unsigned long long d;
                        DUP2(d, __float_as_uint(mv));
                        FMA2(a01[r], wB[kk].x, d);
                        FMA2(a23[r], wB[kk].y, d);
                    }
                }
            }
        }
    }
    __syncthreads();

    {
        const float4 bb = *(const float4*)(b2 + ox4);
        #pragma unroll
        for (int r = 0; r < 4; r++) {
            unsigned u0, u1, u2, u3;
            UNPK2(u0, u1, a01[r]);
            UNPK2(u2, u3, a23[r]);
            *(float4*)(xs + (ry + r) * OUTD + ox4) =
                make_float4(__uint_as_float(u0) + bb.x, __uint_as_float(u1) + bb.y,
                            __uint_as_float(u2) + bb.z, __uint_as_float(u3) + bb.w);
        }
    }
    __syncthreads();

    {
        const int row = w;
        float s = 0.0f, sq = 0.0f;
        #pragma unroll
        for (int j = 0; j < 16; j++) {
            float v = xs[row * OUTD + l + 32 * j];
            s += v; sq += v * v;
        }
        #pragma unroll
        for (int o = 16; o > 0; o >>= 1) {
            s  += __shfl_xor_sync(0xFFFFFFFFu, s, o);
            sq += __shfl_xor_sync(0xFFFFFFFFu, sq, o);
        }
        const float mean = s * (1.0f / OUTD);
        const float var  = sq * (1.0f / OUTD) - mean * mean;
        const float rstd = rsqrtf(var + 1e-5f);
        #pragma unroll
        for (int j = 0; j < 16; j++) {
            const int idx = l + 32 * j;
            float v = xs[row * OUTD + idx];
            xs[row * OUTD + idx] = (v - mean) * rstd * g2[idx] + be2[idx];
        }
    }
    __syncthreads();

    {
        float4* dst = (float4*)(theta + (size_t)row0 * OUTD);
        const float4* src = (const float4*)xs;
        #pragma unroll
        for (int i = 0; i < 4; i++)
            dst[t + 256 * i] = src[t + 256 * i];
    }
}

// ---------------------------------------------------------------------------
// Launch: canonical capture fork-join (validated in R15). Transpose hidden
// under cluster on s2; mlp waits on the join event.
// Output layout: [theta (B*512) | alpha (B*64) | mu (B*256)]
// ---------------------------------------------------------------------------
extern "C" void kernel_launch(void* const* d_in, const int* in_sizes, int n_in,
                              void* d_out, int out_size)
{
    const float* h       = (const float*)d_in[0];
    const float* log_tau = (const float*)d_in[1];
    const float* w1      = (const float*)d_in[2];
    const float* b1      = (const float*)d_in[3];
    const float* g1      = (const float*)d_in[4];
    const float* be1     = (const float*)d_in[5];
    const float* w2      = (const float*)d_in[6];
    const float* b2      = (const float*)d_in[7];
    const float* g2      = (const float*)d_in[8];
    const float* be2     = (const float*)d_in[9];

    const int batch = in_sizes[0] / (NN * DD);

    float* out   = (float*)d_out;
    float* theta = out;
    float* alpha = out + (size_t)batch * OUTD;
    float* mu    = out + (size_t)batch * OUTD + (size_t)batch * NN;

    float* w1t_dev = nullptr;
    float* w2t_dev = nullptr;
    cudaGetSymbolAddress((void**)&w1t_dev, g_w1t);
    cudaGetSymbolAddress((void**)&w2t_dev, g_w2t);

    static cudaStream_t s2 = nullptr;
    static cudaEvent_t evRoot = nullptr, evP = nullptr;
    if (s2 == nullptr) {
        cudaStreamCreateWithFlags(&s2, cudaStreamNonBlocking);
        cudaEventCreateWithFlags(&evRoot, cudaEventDisableTiming);
        cudaEventCreateWithFlags(&evP, cudaEventDisableTiming);
    }

    dim3 tb(32, 8);

    // Fork: enroll s2 in the capture from the origin stream FIRST.
    cudaEventRecord(evRoot, 0);
    cudaStreamWaitEvent(s2, evRoot, 0);

    // s2: weight transpose (hidden under cluster on the origin stream)
    transpose2_kernel<<<384, tb, 0, s2>>>(w1, w2, w1t_dev, w2t_dev);
    cudaEventRecord(evP, s2);

    // origin stream: cluster (independent of transpose)
    cluster_kernel<<<batch, 512>>>(h, log_tau, alpha, mu);

    // Join: mlp needs cluster (same stream) + transpose (event)
    cudaStreamWaitEvent(0, evP, 0);
    mlp_kernel<<<batch / 8, 256>>>(mu, b1, g1, be1, b2, g2, be2, theta);
}

// round 17
// speedup vs baseline: 1.0456x; 1.0456x over previous
#include <cuda_runtime.h>
#include <math.h>

#define BB   4096
#define NN   64
#define DD   256
#define OUTD 512
#define NIT  3

// Transposed weight scratch
__device__ float g_w1t[DD * OUTD];    // [256][512]
__device__ float g_w2t[OUTD * OUTD];  // [512][512]

// ---- packed f32x2 helpers (sm_100+) ----
#define FMA2(d, a, b) asm("fma.rn.f32x2 %0, %1, %2, %0;" : "+l"(d) : "l"(a), "l"(b))
#define DUP2(d, s)    asm("mov.b64 %0, {%1, %1};" : "=l"(d) : "r"(s))
#define UNPK2(lo, hi, d) asm("mov.b64 {%0, %1}, %2;" : "=r"(lo), "=r"(hi) : "l"(d))

__device__ __forceinline__ float wsum(float v) {
    #pragma unroll
    for (int o = 16; o > 0; o >>= 1) v += __shfl_xor_sync(0xFFFFFFFFu, v, o);
    return v;
}

// ---------------------------------------------------------------------------
// Combined transpose for w1 (512x256) and w2 (512x512) in ONE launch.
// ---------------------------------------------------------------------------
__global__ void transpose2_kernel(const float* __restrict__ w1,
                                  const float* __restrict__ w2,
                                  float* __restrict__ w1t,
                                  float* __restrict__ w2t)
{
    __shared__ float tile[32][33];
    const float* in;
    float* out;
    int R, C, bid;
    if (blockIdx.x < 128) {
        in = w1; out = w1t; R = OUTD; C = DD; bid = blockIdx.x;
    } else {
        in = w2; out = w2t; R = OUTD; C = OUTD; bid = blockIdx.x - 128;
    }
    const int tilesX = C / 32;
    const int c0 = (bid % tilesX) * 32;
    const int r0 = (bid / tilesX) * 32;
    const int tx = threadIdx.x;
    const int ty = threadIdx.y;
    #pragma unroll
    for (int i = 0; i < 4; i++)
        tile[ty + 8 * i][tx] = in[(size_t)(r0 + ty + 8 * i) * C + c0 + tx];
    __syncthreads();
    #pragma unroll
    for (int i = 0; i < 4; i++)
        out[(size_t)(c0 + ty + 8 * i) * R + r0 + tx] = tile[tx][ty + 8 * i];
}

// ---------------------------------------------------------------------------
// Kernel 1: soft clustering (R15-exact — best measured at 200.9us total).
// ---------------------------------------------------------------------------
__global__ void __launch_bounds__(512, 2)
cluster_kernel(const float* __restrict__ h,
               const float* __restrict__ log_tau,
               float* __restrict__ out_alpha,   // [B, 64]
               float* __restrict__ out_mu)      // [B, 256]
{
    __shared__ float pmu[16][DD];
    __shared__ float mu_s[DD];
    __shared__ float simv[NN];

    const int b = blockIdx.x;
    const int t = threadIdx.x;
    const int w = t >> 5;
    const int l = t & 31;

    const float* hb = h + (size_t)b * NN * DD;

    float4 hv[4][2];
    #pragma unroll
    for (int r = 0; r < 4; r++) {
        const float* p = hb + (size_t)(4 * w + r) * DD + 4 * l;
        hv[r][0] = *(const float4*)(p);
        hv[r][1] = *(const float4*)(p + 128);
    }

    float tau = expf(log_tau[0]);
    tau = fminf(fmaxf(tau, 0.01f), 2.0f);
    const float inv_tau = 1.0f / tau;

    float rni[4];
    {
        float d[4];
        #pragma unroll
        for (int r = 0; r < 4; r++) {
            float4 a = hv[r][0], c = hv[r][1];
            d[r] = a.x*a.x + a.y*a.y + a.z*a.z + a.w*a.w
                 + c.x*c.x + c.y*c.y + c.z*c.z + c.w*c.w;
        }
        #pragma unroll
        for (int r = 0; r < 4; r++) d[r] += __shfl_xor_sync(0xFFFFFFFFu, d[r], 16);
        float p0 = (l & 16) ? d[1] : d[0];
        float p1 = (l & 16) ? d[3] : d[2];
        p0 += __shfl_xor_sync(0xFFFFFFFFu, p0, 8);
        p1 += __shfl_xor_sync(0xFFFFFFFFu, p1, 8);
        float q = (l & 8) ? p1 : p0;
        q += __shfl_xor_sync(0xFFFFFFFFu, q, 4);
        q += __shfl_xor_sync(0xFFFFFFFFu, q, 2);
        q += __shfl_xor_sync(0xFFFFFFFFu, q, 1);
        float s0 = __shfl_sync(0xFFFFFFFFu, q, 0);
        float s1 = __shfl_sync(0xFFFFFFFFu, q, 16);
        float s2 = __shfl_sync(0xFFFFFFFFu, q, 8);
        float s3 = __shfl_sync(0xFFFFFFFFu, q, 24);
        rni[0] = inv_tau / fmaxf(sqrtf(s0), 1e-12f);
        rni[1] = inv_tau / fmaxf(sqrtf(s1), 1e-12f);
        rni[2] = inv_tau / fmaxf(sqrtf(s2), 1e-12f);
        rni[3] = inv_tau / fmaxf(sqrtf(s3), 1e-12f);
    }

    {
        float pm[8];
        #pragma unroll
        for (int i = 0; i < 8; i++) pm[i] = 0.0f;
        #pragma unroll
        for (int r = 0; r < 4; r++) {
            pm[0] += hv[r][0].x; pm[1] += hv[r][0].y;
            pm[2] += hv[r][0].z; pm[3] += hv[r][0].w;
            pm[4] += hv[r][1].x; pm[5] += hv[r][1].y;
            pm[6] += hv[r][1].z; pm[7] += hv[r][1].w;
        }
        *(float4*)&pmu[w][4 * l]       = make_float4(pm[0], pm[1], pm[2], pm[3]);
        *(float4*)&pmu[w][128 + 4 * l] = make_float4(pm[4], pm[5], pm[6], pm[7]);
    }
    __syncthreads();

    if (t < DD) {
        float acc = 0.0f;
        #pragma unroll
        for (int ww = 0; ww < 16; ww++) acc += pmu[ww][t];
        mu_s[t] = acc * (1.0f / NN);
    }
    __syncthreads();

    for (int it = 0; it < NIT; it++) {
        float4 mn0 = *(const float4*)(mu_s + 4 * l);
        float4 mn1 = *(const float4*)(mu_s + 128 + 4 * l);
        float nq = mn0.x*mn0.x + mn0.y*mn0.y + mn0.z*mn0.z + mn0.w*mn0.w
                 + mn1.x*mn1.x + mn1.y*mn1.y + mn1.z*mn1.z + mn1.w*mn1.w;
        nq = wsum(nq);
        const float inv_nm = 1.0f / fmaxf(sqrtf(nq), 1e-12f);

        {
            float d[4];
            #pragma unroll
            for (int r = 0; r < 4; r++) {
                float4 a = hv[r][0], c = hv[r][1];
                d[r] = (a.x*mn0.x + a.y*mn0.y + a.z*mn0.z + a.w*mn0.w
                      + c.x*mn1.x + c.y*mn1.y + c.z*mn1.z + c.w*mn1.w) * rni[r];
            }
            #pragma unroll
            for (int r = 0; r < 4; r++) d[r] += __shfl_xor_sync(0xFFFFFFFFu, d[r], 16);
            float p0 = (l & 16) ? d[1] : d[0];
            float p1 = (l & 16) ? d[3] : d[2];
            p0 += __shfl_xor_sync(0xFFFFFFFFu, p0, 8);
            p1 += __shfl_xor_sync(0xFFFFFFFFu, p1, 8);
            float q = (l & 8) ? p1 : p0;
            q += __shfl_xor_sync(0xFFFFFFFFu, q, 4);
            q += __shfl_xor_sync(0xFFFFFFFFu, q, 2);
            q += __shfl_xor_sync(0xFFFFFFFFu, q, 1);
            const int rowmap = ((l >> 4) & 1) + (((l >> 3) & 1) << 1);
            if ((l & 7) == 0) simv[4 * w + rowmap] = q * inv_nm;
        }
        __syncthreads();

        // warp-redundant softmax over 64; shift by simv[0] (broadcast, exact)
        float s0 = simv[l];
        float s1 = simv[l + 32];
        const float shift = __shfl_sync(0xFFFFFFFFu, s0, 0);
        float e0 = expf(s0 - shift);
        float e1 = expf(s1 - shift);
        float inv = 1.0f / wsum(e0 + e1);
        float a_lo = e0 * inv;
        float a_hi = e1 * inv;

        if (it == NIT - 1 && w == 0) {
            out_alpha[(size_t)b * NN + l]      = a_lo;
            out_alpha[(size_t)b * NN + l + 32] = a_hi;
        }

        float al[4];
        if (w < 8) {
            #pragma unroll
            for (int r = 0; r < 4; r++)
                al[r] = __shfl_sync(0xFFFFFFFFu, a_lo, 4 * w + r);
        } else {
            #pragma unroll
            for (int r = 0; r < 4; r++)
                al[r] = __shfl_sync(0xFFFFFFFFu, a_hi, 4 * w + r - 32);
        }

        float pm[8];
        #pragma unroll
        for (int i = 0; i < 8; i++) pm[i] = 0.0f;
        #pragma unroll
        for (int r = 0; r < 4; r++) {
            const float a = al[r];
            pm[0] += a * hv[r][0].x; pm[1] += a * hv[r][0].y;
            pm[2] += a * hv[r][0].z; pm[3] += a * hv[r][0].w;
            pm[4] += a * hv[r][1].x; pm[5] += a * hv[r][1].y;
            pm[6] += a * hv[r][1].z; pm[7] += a * hv[r][1].w;
        }
        *(float4*)&pmu[w][4 * l]       = make_float4(pm[0], pm[1], pm[2], pm[3]);
        *(float4*)&pmu[w][128 + 4 * l] = make_float4(pm[4], pm[5], pm[6], pm[7]);
        __syncthreads();

        if (t < DD) {
            float acc = 0.0f;
            #pragma unroll
            for (int ww = 0; ww < 16; ww++) acc += pmu[ww][t];
            if (it == NIT - 1) out_mu[(size_t)b * DD + t] = acc;
            else               mu_s[t] = acc;
        }
        if (it < NIT - 1) __syncthreads();
    }
}

// ---------------------------------------------------------------------------
// Kernel 2: fused MLP (R11 core). LN2 now writes DIRECTLY to gmem
// (coalesced), deleting the final smem roundtrip + barrier + copy.
// ---------------------------------------------------------------------------
__global__ void __launch_bounds__(256, 3)
mlp_kernel(const float* __restrict__ mu_in,
           const float* __restrict__ b1,
           const float* __restrict__ g1,
           const float* __restrict__ be1,
           const float* __restrict__ b2,
           const float* __restrict__ g2,
           const float* __restrict__ be2,
           float* __restrict__ theta)
{
    __shared__ float xs[8 * OUTD];

    const int t = threadIdx.x;
    const int row0 = blockIdx.x * 8;
    const int ox4 = (t & 127) * 4;
    const int ry = (t >> 7) * 4;
    const int w = t >> 5;
    const int l = t & 31;

    {
        const float4* src = (const float4*)(mu_in + (size_t)row0 * DD);
        float4* dst = (float4*)xs;
        dst[t]       = src[t];
        dst[t + 256] = src[t + 256];
    }
    __syncthreads();

    unsigned long long a01[4], a23[4];
    #pragma unroll
    for (int r = 0; r < 4; r++) { a01[r] = 0ull; a23[r] = 0ull; }

    {
        const float* wb = g_w1t + ox4;
        ulonglong2 wA[4], wB[4];
        #pragma unroll
        for (int kk = 0; kk < 4; kk++)
            wA[kk] = *(const ulonglong2*)(wb + (size_t)kk * OUTD);

        for (int k = 0; k < DD; k += 8) {
            #pragma unroll
            for (int kk = 0; kk < 4; kk++)
                wB[kk] = *(const ulonglong2*)(wb + (size_t)(k + 4 + kk) * OUTD);
            {
                float4 m[4];
                #pragma unroll
                for (int r = 0; r < 4; r++)
                    m[r] = *(const float4*)(xs + (ry + r) * DD + k);
                #pragma unroll
                for (int kk = 0; kk < 4; kk++) {
                    #pragma unroll
                    for (int r = 0; r < 4; r++) {
                        float mv = (kk == 0) ? m[r].x : (kk == 1) ? m[r].y
                                 : (kk == 2) ? m[r].z : m[r].w;
                        unsigned long long d;
                        DUP2(d, __float_as_uint(mv));
                        FMA2(a01[r], wA[kk].x, d);
                        FMA2(a23[r], wA[kk].y, d);
                    }
                }
            }
            const int kn = (k + 8 < DD) ? k + 8 : k;
            #pragma unroll
            for (int kk = 0; kk < 4; kk++)
                wA[kk] = *(const ulonglong2*)(wb + (size_t)(kn + kk) * OUTD);
            {
                float4 m[4];
                #pragma unroll
                for (int r = 0; r < 4; r++)
                    m[r] = *(const float4*)(xs + (ry + r) * DD + k + 4);
                #pragma unroll
                for (int kk = 0; kk < 4; kk++) {
                    #pragma unroll
                    for (int r = 0; r < 4; r++) {
                        float mv = (kk == 0) ? m[r].x : (kk == 1) ? m[r].y
                                 : (kk == 2) ? m[r].z : m[r].w;
                        unsigned long long d;
                        DUP2(d, __float_as_uint(mv));
                        FMA2(a01[r], wB[kk].x, d);
                        FMA2(a23[r], wB[kk].y, d);
                    }
                }
            }
        }
    }
    __syncthreads();

    {
        const float4 bb = *(const float4*)(b1 + ox4);
        #pragma unroll
        for (int r = 0; r < 4; r++) {
            unsigned u0, u1, u2, u3;
            UNPK2(u0, u1, a01[r]);
            UNPK2(u2, u3, a23[r]);
            *(float4*)(xs + (ry + r) * OUTD + ox4) =
                make_float4(__uint_as_float(u0) + bb.x, __uint_as_float(u1) + bb.y,
                            __uint_as_float(u2) + bb.z, __uint_as_float(u3) + bb.w);
        }
    }
    __syncthreads();

    {
        const int row = w;
        float s = 0.0f, sq = 0.0f;
        #pragma unroll
        for (int j = 0; j < 16; j++) {
            float v = xs[row * OUTD + l + 32 * j];
            s += v; sq += v * v;
        }
        #pragma unroll
        for (int o = 16; o > 0; o >>= 1) {
            s  += __shfl_xor_sync(0xFFFFFFFFu, s, o);
            sq += __shfl_xor_sync(0xFFFFFFFFu, sq, o);
        }
        const float mean = s * (1.0f / OUTD);
        const float var  = sq * (1.0f / OUTD) - mean * mean;
        const float rstd = rsqrtf(var + 1e-5f);
        #pragma unroll
        for (int j = 0; j < 16; j++) {
            const int idx = l + 32 * j;
            float v = xs[row * OUTD + idx];
            v = (v - mean) * rstd * g1[idx] + be1[idx];
            v = 0.5f * v * (1.0f + erff(v * 0.70710678118654752f));
            xs[row * OUTD + idx] = v;
        }
    }
    __syncthreads();

    #pragma unroll
    for (int r = 0; r < 4; r++) { a01[r] = 0ull; a23[r] = 0ull; }

    {
        const float* wb = g_w2t + ox4;
        ulonglong2 wA[4], wB[4];
        #pragma unroll
        for (int kk = 0; kk < 4; kk++)
            wA[kk] = *(const ulonglong2*)(wb + (size_t)kk * OUTD);

        for (int k = 0; k < OUTD; k += 8) {
            #pragma unroll
            for (int kk = 0; kk < 4; kk++)
                wB[kk] = *(const ulonglong2*)(wb + (size_t)(k + 4 + kk) * OUTD);
            {
                float4 m[4];
                #pragma unroll
                for (int r = 0; r < 4; r++)
                    m[r] = *(const float4*)(xs + (ry + r) * OUTD + k);
                #pragma unroll
                for (int kk = 0; kk < 4; kk++) {
                    #pragma unroll
                    for (int r = 0; r < 4; r++) {
                        float mv = (kk == 0) ? m[r].x : (kk == 1) ? m[r].y
                                 : (kk == 2) ? m[r].z : m[r].w;
                        unsigned long long d;
                        DUP2(d, __float_as_uint(mv));
                        FMA2(a01[r], wA[kk].x, d);
                        FMA2(a23[r], wA[kk].y, d);
                    }
                }
            }
            const int kn = (k + 8 < OUTD) ? k + 8 : k;
            #pragma unroll
            for (int kk = 0; kk < 4; kk++)
                wA[kk] = *(const ulonglong2*)(wb + (size_t)(kn + kk) * OUTD);
            {
                float4 m[4];
                #pragma unroll
                for (int r = 0; r < 4; r++)
                    m[r] = *(const float4*)(xs + (ry + r) * OUTD + k + 4);
                #pragma unroll
                for (int kk = 0; kk < 4; kk++) {
                    #pragma unroll
                    for (int r = 0; r < 4; r++) {
                        float mv = (kk == 0) ? m[r].x : (kk == 1) ? m[r].y
                                 : (kk == 2) ? m[r].z : m[r].w;
                        unsigned long long d;
                        DUP2(d, __float_as_uint(mv));
                        FMA2(a01[r], wB[kk].x, d);
                        FMA2(a23[r], wB[kk].y, d);
                    }
                }
            }
        }
    }
    __syncthreads();

    // --- y2 + b2 into xs ---
    {
        const float4 bb = *(const float4*)(b2 + ox4);
        #pragma unroll
        for (int r = 0; r < 4; r++) {
            unsigned u0, u1, u2, u3;
            UNPK2(u0, u1, a01[r]);
            UNPK2(u2, u3, a23[r]);
            *(float4*)(xs + (ry + r) * OUTD + ox4) =
                make_float4(__uint_as_float(u0) + bb.x, __uint_as_float(u1) + bb.y,
                            __uint_as_float(u2) + bb.z, __uint_as_float(u3) + bb.w);
        }
    }
    __syncthreads();

    // --- LN2: normalize and write DIRECTLY to gmem (coalesced) ---
    {
        const int row = w;
        float s = 0.0f, sq = 0.0f;
        #pragma unroll
        for (int j = 0; j < 16; j++) {
            float v = xs[row * OUTD + l + 32 * j];
            s += v; sq += v * v;
        }
        #pragma unroll
        for (int o = 16; o > 0; o >>= 1) {
            s  += __shfl_xor_sync(0xFFFFFFFFu, s, o);
            sq += __shfl_xor_sync(0xFFFFFFFFu, sq, o);
        }
        const float mean = s * (1.0f / OUTD);
        const float var  = sq * (1.0f / OUTD) - mean * mean;
        const float rstd = rsqrtf(var + 1e-5f);
        float* dst = theta + (size_t)(row0 + row) * OUTD;
        #pragma unroll
        for (int j = 0; j < 16; j++) {
            const int idx = l + 32 * j;
            float v = xs[row * OUTD + idx];
            dst[idx] = (v - mean) * rstd * g2[idx] + be2[idx];
        }
    }
}

// ---------------------------------------------------------------------------
// Launch: canonical capture fork-join (validated R15). Transpose hidden
// under cluster on s2; mlp waits on the join event.
// Output layout: [theta (B*512) | alpha (B*64) | mu (B*256)]
// ---------------------------------------------------------------------------
extern "C" void kernel_launch(void* const* d_in, const int* in_sizes, int n_in,
                              void* d_out, int out_size)
{
    const float* h       = (const float*)d_in[0];
    const float* log_tau = (const float*)d_in[1];
    const float* w1      = (const float*)d_in[2];
    const float* b1      = (const float*)d_in[3];
    const float* g1      = (const float*)d_in[4];
    const float* be1     = (const float*)d_in[5];
    const float* w2      = (const float*)d_in[6];
    const float* b2      = (const float*)d_in[7];
    const float* g2      = (const float*)d_in[8];
    const float* be2     = (const float*)d_in[9];

    const int batch = in_sizes[0] / (NN * DD);

    float* out   = (float*)d_out;
    float* theta = out;
    float* alpha = out + (size_t)batch * OUTD;
    float* mu    = out + (size_t)batch * OUTD + (size_t)batch * NN;

    float* w1t_dev = nullptr;
    float* w2t_dev = nullptr;
    cudaGetSymbolAddress((void**)&w1t_dev, g_w1t);
    cudaGetSymbolAddress((void**)&w2t_dev, g_w2t);

    static cudaStream_t s2 = nullptr;
    static cudaEvent_t evRoot = nullptr, evP = nullptr;
    if (s2 == nullptr) {
        cudaStreamCreateWithFlags(&s2, cudaStreamNonBlocking);
        cudaEventCreateWithFlags(&evRoot, cudaEventDisableTiming);
        cudaEventCreateWithFlags(&evP, cudaEventDisableTiming);
    }

    dim3 tb(32, 8);

    // Fork: enroll s2 in the capture from the origin stream FIRST.
    cudaEventRecord(evRoot, 0);
    cudaStreamWaitEvent(s2, evRoot, 0);

    // s2: weight transpose (hidden under cluster on the origin stream)
    transpose2_kernel<<<384, tb, 0, s2>>>(w1, w2, w1t_dev, w2t_dev);
    cudaEventRecord(evP, s2);

    // origin stream: cluster (independent of transpose)
    cluster_kernel<<<batch, 512>>>(h, log_tau, alpha, mu);

    // Join: mlp needs cluster (same stream) + transpose (event)
    cudaStreamWaitEvent(0, evP, 0);
    mlp_kernel<<<batch / 8, 256>>>(mu, b1, g1, be1, b2, g2, be2, theta);
}